// round 11
// baseline (speedup 1.0000x reference)
#include <cuda_runtime.h>
#include <cuda_fp16.h>
#include <math.h>
#include <stdint.h>

#define B_   4
#define C_   512
#define T_   32
#define HW_  1024
#define NCOL (T_*HW_)            // 32768 pixels (n) per batch
#define TOT  (B_*C_*T_*HW_)

// Scratch
__device__ __half d_x16[TOT];      // fp16 x, [b][n][c]  (n = t*1024+hw)
__device__ __half d_W16[1024*512]; // W2G = W2·diag(gamma), [m][k], fp16
__device__ __half d_u16[TOT];      // u  (fp16, [b][n][c])
__device__ __half d_vp16[TOT];     // v' (fp16, [b][n][c])
__device__ float  d_w2g1[1024];
__device__ float  d_w2b[1024];
__device__ float  d_psum[16384];
__device__ float  d_psum2[16384];
__device__ float  d_mean[B_*T_];
__device__ float  d_rstd[B_*T_];

__device__ __forceinline__ void cp16g(void* dst, const void* src) {
    unsigned d = (unsigned)__cvta_generic_to_shared(dst);
    asm volatile("cp.async.cg.shared.global [%0], [%1], 16;\n" :: "r"(d), "l"(src));
}

#define MMA_F16(d0,d1,d2,d3,a0,a1,a2,a3,b0,b1) \
    asm volatile("mma.sync.aligned.m16n8k16.row.col.f32.f16.f16.f32 " \
                 "{%0,%1,%2,%3},{%4,%5,%6,%7},{%8,%9},{%0,%1,%2,%3};" \
                 : "+f"(d0), "+f"(d1), "+f"(d2), "+f"(d3) \
                 : "r"(a0), "r"(a1), "r"(a2), "r"(a3), "r"(b0), "r"(b1))

// ---------------------------------------------------------------------------
// prep_w2 (unchanged)
// ---------------------------------------------------------------------------
__global__ void prep_w2(const float* __restrict__ wq, const float* __restrict__ wk,
                        const float* __restrict__ wv, const float* __restrict__ wproj,
                        const float* __restrict__ gamma, const float* __restrict__ beta)
{
    int m = blockIdx.x;
    int tid = threadIdx.x;
    float lg = 0.f, lb = 0.f;
    #pragma unroll
    for (int jj = 0; jj < 2; jj++) {
        int j = jj * 256 + tid;
        float acc = 0.f;
        if (m < 512) {
            #pragma unroll 4
            for (int o = 0; o < 512; o++)
                acc += wq[o*512 + m] * wk[o*512 + j];
        } else {
            int i = m - 512;
            #pragma unroll 4
            for (int c = 0; c < 512; c++)
                acc += wproj[i*512 + c] * wv[c*512 + j];
        }
        __half wh = __float2half(acc * gamma[j]);
        d_W16[(size_t)m * 512 + j] = wh;
        lg += __half2float(wh);
        lb += acc * beta[j];
    }
    __shared__ float red[16];
    #pragma unroll
    for (int o = 16; o > 0; o >>= 1) {
        lg += __shfl_down_sync(0xffffffffu, lg, o);
        lb += __shfl_down_sync(0xffffffffu, lb, o);
    }
    int w = tid >> 5;
    if ((tid & 31) == 0) { red[w] = lg; red[8 + w] = lb; }
    __syncthreads();
    if (tid == 0) {
        float G = 0.f, Bv = 0.f;
        for (int k = 0; k < 8; k++) { G += red[k]; Bv += red[8 + k]; }
        d_w2g1[m] = G;
        d_w2b[m]  = Bv;
    }
}

// ---------------------------------------------------------------------------
// conv_x16 + LN partial sums (unchanged)
// ---------------------------------------------------------------------------
__global__ void conv_x16(const float* __restrict__ x)
{
    __shared__ float sT[64][65];
    __shared__ float rsum[8], rsum2[8];
    int b   = blockIdx.z;
    int c0  = blockIdx.y * 64;
    int n0t = blockIdx.x * 64;
    int tid = threadIdx.x;
    const float* xb = x + (size_t)b * C_ * NCOL;
    float s = 0.f, ss = 0.f;
    #pragma unroll
    for (int r = 0; r < 4; r++) {
        int flat = r * 256 + tid;
        int cr = flat >> 4, nq = flat & 15;
        float4 v = *reinterpret_cast<const float4*>(
            xb + (size_t)(c0 + cr) * NCOL + n0t + nq * 4);
        sT[cr][nq*4+0] = v.x; sT[cr][nq*4+1] = v.y;
        sT[cr][nq*4+2] = v.z; sT[cr][nq*4+3] = v.w;
        s  += v.x + v.y + v.z + v.w;
        ss += v.x*v.x + v.y*v.y + v.z*v.z + v.w*v.w;
    }
    #pragma unroll
    for (int o = 16; o > 0; o >>= 1) {
        s  += __shfl_down_sync(0xffffffffu, s,  o);
        ss += __shfl_down_sync(0xffffffffu, ss, o);
    }
    if ((tid & 31) == 0) { rsum[tid >> 5] = s; rsum2[tid >> 5] = ss; }
    __syncthreads();
    if (tid == 0) {
        float S = 0.f, SS = 0.f;
        #pragma unroll
        for (int k = 0; k < 8; k++) { S += rsum[k]; SS += rsum2[k]; }
        int t = blockIdx.x >> 4, nIn = blockIdx.x & 15;
        int pid = ((b * 32 + t) * 8 + blockIdx.y) * 16 + nIn;
        d_psum[pid]  = S;
        d_psum2[pid] = SS;
    }
    int nr = tid >> 2, cq = tid & 3;
    uint32_t pk[8];
    #pragma unroll
    for (int j = 0; j < 8; j++) {
        __half2 h2 = __floats2half2_rn(sT[cq*16 + j*2][nr], sT[cq*16 + j*2 + 1][nr]);
        pk[j] = *reinterpret_cast<uint32_t*>(&h2);
    }
    __half* dst = d_x16 + ((size_t)b * NCOL + n0t + nr) * 512 + c0 + cq * 16;
    *reinterpret_cast<uint4*>(dst)     = make_uint4(pk[0], pk[1], pk[2], pk[3]);
    *reinterpret_cast<uint4*>(dst + 8) = make_uint4(pk[4], pk[5], pk[6], pk[7]);
}

__global__ void reduce_stats()
{
    int g = blockIdx.x;
    int tid = threadIdx.x;
    float s  = d_psum[g * 128 + tid];
    float ss = d_psum2[g * 128 + tid];
    #pragma unroll
    for (int o = 16; o > 0; o >>= 1) {
        s  += __shfl_down_sync(0xffffffffu, s,  o);
        ss += __shfl_down_sync(0xffffffffu, ss, o);
    }
    __shared__ float sm[8];
    if ((tid & 31) == 0) { sm[tid >> 5] = s; sm[4 + (tid >> 5)] = ss; }
    __syncthreads();
    if (tid == 0) {
        float S = sm[0] + sm[1] + sm[2] + sm[3];
        float SS = sm[4] + sm[5] + sm[6] + sm[7];
        float invn = 1.f / (float)(C_ * HW_);
        float m = S * invn;
        float var = SS * invn - m * m;
        d_mean[g] = m;
        d_rstd[g] = rsqrtf(var + 1e-6f);
    }
}

// ---------------------------------------------------------------------------
// fp16 GEMM (operands swapped): D[pixel][channel] = x16·W16^T.
// Epilogue: u16/vp16 = fp16(rstd·acc + bias(channel)) written [n][c].
// ---------------------------------------------------------------------------
#define AROW 40
#define STH  (128*AROW)
#define STAGEH (2*STH)
#define GEMM_SMEM (4*STAGEH*2)   // 81920 B

__global__ __launch_bounds__(128, 2) void gemm_uv_f16()
{
    extern __shared__ __half smh[];
    int b   = blockIdx.z;
    int n0  = blockIdx.x * 128;       // channel tile (fast dim -> x tile L2 reuse)
    int m0p = blockIdx.y * 128;       // pixel tile (within single t)
    const __half* xb = d_x16 + (size_t)b * NCOL * 512;
    int tid  = threadIdx.x;
    int lane = tid & 31;
    int w    = tid >> 5;
    int warpM = w >> 1, warpN = w & 1;
    int g = lane >> 2, tq = lane & 3;
    int am = warpM * 64 + g;          // pixel rows
    int bn = warpN * 64 + g;          // channel rows

    float acc[4][8][4];
    #pragma unroll
    for (int i = 0; i < 4; i++)
        #pragma unroll
        for (int j = 0; j < 8; j++)
            #pragma unroll
            for (int r = 0; r < 4; r++) acc[i][j][r] = 0.f;

    auto load_stage = [&](int k0, int buf) {
        __half* As = smh + buf * STAGEH;
        __half* Bs = As + STH;
        #pragma unroll
        for (int r = 0; r < 4; r++) {
            int ch = r * 128 + tid;
            int row = ch >> 2;
            int q   = ch & 3;
            cp16g(As + row * AROW + q * 8, &xb[(size_t)(m0p + row) * 512 + k0 + q * 8]);
            cp16g(Bs + row * AROW + q * 8, &d_W16[(size_t)(n0 + row) * 512 + k0 + q * 8]);
        }
    };

    #pragma unroll
    for (int p = 0; p < 3; p++) {
        load_stage(p * 32, p);
        asm volatile("cp.async.commit_group;\n");
    }

    for (int it = 0; it < 16; it++) {
        asm volatile("cp.async.wait_group 2;\n");
        __syncthreads();

        const uint32_t* Asw = reinterpret_cast<const uint32_t*>(smh + (it & 3) * STAGEH);
        const uint32_t* Bsw = Asw + STH / 2;

        #pragma unroll
        for (int ks = 0; ks < 16; ks += 8) {
            uint32_t a[4][4], bq[8][2];
            #pragma unroll
            for (int mf = 0; mf < 4; mf++) {
                int r0 = (am + mf * 16) * 20 + ks + tq;
                int r1 = (am + mf * 16 + 8) * 20 + ks + tq;
                a[mf][0] = Asw[r0];
                a[mf][1] = Asw[r1];
                a[mf][2] = Asw[r0 + 4];
                a[mf][3] = Asw[r1 + 4];
            }
            #pragma unroll
            for (int nf = 0; nf < 8; nf++) {
                int rb = (bn + nf * 8) * 20 + ks + tq;
                bq[nf][0] = Bsw[rb];
                bq[nf][1] = Bsw[rb + 4];
            }
            #pragma unroll
            for (int mf = 0; mf < 4; mf++)
                #pragma unroll
                for (int nf = 0; nf < 8; nf++)
                    MMA_F16(acc[mf][nf][0], acc[mf][nf][1], acc[mf][nf][2], acc[mf][nf][3],
                            a[mf][0], a[mf][1], a[mf][2], a[mf][3],
                            bq[nf][0], bq[nf][1]);
        }
        if (it + 3 < 16)
            load_stage((it + 3) * 32, (it + 3) & 3);
        asm volatile("cp.async.commit_group;\n");
    }

    // epilogue: per-column (channel) bias, [n][c] fp16 outputs
    int t = blockIdx.y >> 3;
    int gidx = b * 32 + t;
    float rstdv = d_rstd[gidx];
    float rm    = rstdv * d_mean[gidx];
    bool isU = (n0 < 512);
    __half* outb = (isU ? d_u16 : d_vp16) + (size_t)b * NCOL * 512;
    int choff = isU ? 0 : 512;
    float biasA[8], biasB[8];
    int cbase[8];
    #pragma unroll
    for (int nf = 0; nf < 8; nf++) {
        int cn = n0 + warpN * 64 + nf * 8 + tq * 2;
        biasA[nf] = d_w2b[cn]     - rm * d_w2g1[cn];
        biasB[nf] = d_w2b[cn + 1] - rm * d_w2g1[cn + 1];
        cbase[nf] = cn - choff;
    }
    #pragma unroll
    for (int mf = 0; mf < 4; mf++) {
        int p0 = m0p + warpM * 64 + mf * 16 + g;
        #pragma unroll
        for (int nf = 0; nf < 8; nf++) {
            __half2 lo = __floats2half2_rn(rstdv * acc[mf][nf][0] + biasA[nf],
                                           rstdv * acc[mf][nf][1] + biasB[nf]);
            __half2 hi = __floats2half2_rn(rstdv * acc[mf][nf][2] + biasA[nf],
                                           rstdv * acc[mf][nf][3] + biasB[nf]);
            *reinterpret_cast<__half2*>(outb + (size_t)p0 * 512 + cbase[nf])       = lo;
            *reinterpret_cast<__half2*>(outb + (size_t)(p0 + 8) * 512 + cbase[nf]) = hi;
        }
    }
}

// ---------------------------------------------------------------------------
// All-fp16 attention. Block = 8 pixels, warp = pixel. [n][c] inputs.
// smem layout (bytes): HX 2x12416 | US 2x12416 | GS 33792 | GH 18432 | misc.
// OS aliases HX in phase 4.
// ---------------------------------------------------------------------------
#define ATTN_SMEM 104448

__global__ __launch_bounds__(256, 2) void attn_f16(const float* __restrict__ x,
                                                   const float* __restrict__ gamma,
                                                   const float* __restrict__ beta,
                                                   float* __restrict__ out)
{
    extern __shared__ char smraw[];
    __half*  HX   = reinterpret_cast<__half*>(smraw);            // [2][px8*776]
    __half*  US   = reinterpret_cast<__half*>(smraw + 24832);    // [2][px8*776]
    float*   GS   = reinterpret_cast<float*>(smraw + 49664);     // px*1056 + t*33 + s
    __half*  GH   = reinterpret_cast<__half*>(smraw + 83456);    // px*1152 + t*36 + s
    float*   gus  = reinterpret_cast<float*>(smraw + 101888);    // [s32*8+px]
    float*   bus  = reinterpret_cast<float*>(smraw + 102912);
    float*   smGf = reinterpret_cast<float*>(smraw + 103936);    // [2][16]
    float*   smBf = reinterpret_cast<float*>(smraw + 104064);
    __half2* gh2  = reinterpret_cast<__half2*>(smraw + 104192);  // [2][8]
    float*   OS   = reinterpret_cast<float*>(smraw);             // alias HX (phase4)

    int blk = blockIdx.x, b = blk >> 7, hw0 = (blk & 127) * 8;
    int tid = threadIdx.x, lane = tid & 31, px = tid >> 5;
    int g = lane >> 2, tq = lane & 3;
    const __half* xh = d_x16  + (size_t)b * NCOL * 512;
    const __half* uh = d_u16  + (size_t)b * NCOL * 512;
    const __half* vh = d_vp16 + (size_t)b * NCOL * 512;

    // staging thread map: flat = r*256+tid -> q=flat&1, pxl=(flat>>1)&7, row=flat>>4
    uint4 xr[2];
    auto ldx = [&](int c0) {
        #pragma unroll
        for (int r = 0; r < 2; r++) {
            int f = r * 256 + tid;
            int q = f & 1, pxl = (f >> 1) & 7, t = f >> 4;
            xr[r] = *reinterpret_cast<const uint4*>(
                xh + ((size_t)t * 1024 + hw0 + pxl) * 512 + c0 + q * 8);
        }
    };
    auto stx = [&](int buf) {
        #pragma unroll
        for (int r = 0; r < 2; r++) {
            int f = r * 256 + tid;
            int q = f & 1, pxl = (f >> 1) & 7, t = f >> 4;
            __half2* d = reinterpret_cast<__half2*>(HX + buf * 6208 + pxl * 776 + t * 24 + q * 8);
            const __half2* sv = reinterpret_cast<const __half2*>(&xr[r]);
            #pragma unroll
            for (int j = 0; j < 4; j++)
                d[j] = __hmul2(sv[j], gh2[buf * 8 + q * 4 + j]);
        }
    };
    auto cp_row16 = [&](const __half* src, __half* dstbase, int c0, int buf) {
        #pragma unroll
        for (int r = 0; r < 2; r++) {
            int f = r * 256 + tid;
            int q = f & 1, pxl = (f >> 1) & 7, s = f >> 4;
            cp16g(dstbase + buf * 6208 + pxl * 776 + s * 24 + q * 8,
                  src + ((size_t)s * 1024 + hw0 + pxl) * 512 + c0 + q * 8);
        }
        asm volatile("cp.async.commit_group;\n");
    };

    // ---------------- phase 1 ----------------
    float acc1[2][4][4];
    #pragma unroll
    for (int i = 0; i < 2; i++)
        #pragma unroll
        for (int j = 0; j < 4; j++)
            #pragma unroll
            for (int r = 0; r < 4; r++) acc1[i][j][r] = 0.f;
    float gu = 0.f, bu = 0.f;

    if (tid < 8)  gh2[tid] = __floats2half2_rn(gamma[2*tid], gamma[2*tid+1]);
    if (tid < 16) { smGf[tid] = gamma[tid]; smBf[tid] = beta[tid]; }
    cp_row16(uh, US, 0, 0);
    ldx(0);
    __syncthreads();

    for (int i = 0; i < 32; i++) {
        int buf = i & 1, c0 = i * 16;
        if (i + 1 < 32) {
            if (tid < 8)
                gh2[(buf^1)*8 + tid] = __floats2half2_rn(gamma[c0+16+2*tid], gamma[c0+17+2*tid]);
            if (tid >= 32 && tid < 48) {
                int j = tid - 32;
                smGf[(buf^1)*16 + j] = gamma[c0 + 16 + j];
                smBf[(buf^1)*16 + j] = beta[c0 + 16 + j];
            }
        }
        stx(buf);
        asm volatile("cp.async.wait_group 0;\n");
        __syncthreads();
        if (i + 1 < 32) { cp_row16(uh, US, c0 + 16, buf ^ 1); ldx(c0 + 16); }

        const uint32_t* Hw = reinterpret_cast<const uint32_t*>(HX + buf * 6208) + px * 388;
        const uint32_t* Uw = reinterpret_cast<const uint32_t*>(US + buf * 6208) + px * 388;
        uint32_t a[2][4], bq[4][2];
        #pragma unroll
        for (int mf = 0; mf < 2; mf++) {
            int row = (mf * 16 + g) * 12;
            a[mf][0] = Hw[row + tq];
            a[mf][1] = Hw[row + 96 + tq];
            a[mf][2] = Hw[row + tq + 4];
            a[mf][3] = Hw[row + 96 + tq + 4];
        }
        #pragma unroll
        for (int nf = 0; nf < 4; nf++) {
            int rb = (nf * 8 + g) * 12;
            bq[nf][0] = Uw[rb + tq];
            bq[nf][1] = Uw[rb + tq + 4];
        }
        #pragma unroll
        for (int mf = 0; mf < 2; mf++)
            #pragma unroll
            for (int nf = 0; nf < 4; nf++)
                MMA_F16(acc1[mf][nf][0], acc1[mf][nf][1], acc1[mf][nf][2], acc1[mf][nf][3],
                        a[mf][0], a[mf][1], a[mf][2], a[mf][3],
                        bq[nf][0], bq[nf][1]);

        // gu/bu: thread = (px = tid>>5, s = lane)
        const __half2* ur = reinterpret_cast<const __half2*>(US + buf * 6208 + px * 776 + lane * 24);
        #pragma unroll
        for (int j = 0; j < 8; j++) {
            float2 uf = __half22float2(ur[j]);
            gu += smGf[buf*16 + 2*j] * uf.x + smGf[buf*16 + 2*j + 1] * uf.y;
            bu += smBf[buf*16 + 2*j] * uf.x + smBf[buf*16 + 2*j + 1] * uf.y;
        }
    }

    gus[lane * 8 + px] = gu;
    bus[lane * 8 + px] = bu;
    __syncthreads();

    // corrected, scaled logits -> GS
    const float scale = 0.044194173824159216f;
    #pragma unroll
    for (int mf = 0; mf < 2; mf++) {
        int t0 = mf * 16 + g, t1 = t0 + 8;
        float r0 = d_rstd[b*32 + t0], m0v = d_mean[b*32 + t0];
        float r1 = d_rstd[b*32 + t1], m1v = d_mean[b*32 + t1];
        #pragma unroll
        for (int nf = 0; nf < 4; nf++) {
            int s0 = nf * 8 + tq * 2, s1 = s0 + 1;
            float gu0 = gus[s0*8 + px], bu0 = bus[s0*8 + px];
            float gu1 = gus[s1*8 + px], bu1 = bus[s1*8 + px];
            GS[px*1056 + t0*33 + s0] = (r0*(acc1[mf][nf][0] - m0v*gu0) + bu0) * scale;
            GS[px*1056 + t0*33 + s1] = (r0*(acc1[mf][nf][1] - m0v*gu1) + bu1) * scale;
            GS[px*1056 + t1*33 + s0] = (r1*(acc1[mf][nf][2] - m0v*0.f - m1v*gu0 + 0.f) + bu0) * scale;
            GS[px*1056 + t1*33 + s1] = (r1*(acc1[mf][nf][3] - m1v*gu1) + bu1) * scale;
        }
    }
    __syncthreads();

    // softmax + fp16 pack (thread = (px = tid>>5, t = lane))
    {
        float* grow = GS + px * 1056 + lane * 33;
        __half2* ghrow = reinterpret_cast<__half2*>(GH + px * 1152 + lane * 36);
        int t = lane;
        float mx = -1e30f;
        for (int s = 0; s <= t; s++) mx = fmaxf(mx, grow[s]);
        float Z = 0.f;
        for (int s = 0; s <= t; s++) Z += __expf(grow[s] - mx);
        float iz = 1.f / Z;
        #pragma unroll
        for (int s = 0; s < 32; s += 2) {
            float w0 = (s     <= t) ? __expf(grow[s]     - mx) * iz : 0.f;
            float w1 = (s + 1 <= t) ? __expf(grow[s + 1] - mx) * iz : 0.f;
            ghrow[s >> 1] = __floats2half2_rn(w0, w1);
        }
    }
    __syncthreads();

    // ---------------- phase 4: out = G @ vp + x ----------------
    cp_row16(vh, US, 0, 0);
    for (int i = 0; i < 32; i++) {
        int buf = i & 1, oc = i * 16;
        asm volatile("cp.async.wait_group 0;\n");
        __syncthreads();
        if (i + 1 < 32) cp_row16(vh, US, oc + 16, buf ^ 1);

        // residual x loads (consumed at end)
        float4 xa[2][2];
        #pragma unroll
        for (int r = 0; r < 2; r++) {
            int row = r * 256 + tid;
            int o = row >> 5, t = row & 31;
            const float* xb2 = x + ((size_t)((b*512 + oc + o) * 32 + t)) * 1024 + hw0;
            xa[r][0] = *reinterpret_cast<const float4*>(xb2);
            xa[r][1] = *reinterpret_cast<const float4*>(xb2 + 4);
        }

        float acc2[2][2][4];
        #pragma unroll
        for (int ii = 0; ii < 2; ii++)
            #pragma unroll
            for (int j = 0; j < 2; j++)
                #pragma unroll
                for (int r = 0; r < 4; r++) acc2[ii][j][r] = 0.f;

        const uint32_t* Gw = reinterpret_cast<const uint32_t*>(GH) + px * 576;
        const __half* Vb = US + buf * 6208 + px * 776;
        #pragma unroll
        for (int k0 = 0; k0 < 32; k0 += 16) {
            uint32_t a[2][4], bq[2][2];
            #pragma unroll
            for (int mf = 0; mf < 2; mf++) {
                int wb = (mf * 16 + g) * 18 + (k0 >> 1);
                a[mf][0] = Gw[wb + tq];
                a[mf][1] = Gw[wb + 144 + tq];
                a[mf][2] = Gw[wb + tq + 4];
                a[mf][3] = Gw[wb + 144 + tq + 4];
            }
            #pragma unroll
            for (int nf = 0; nf < 2; nf++) {
                int col = nf * 8 + g;
                uint32_t l0 = __half_as_ushort(Vb[(k0 + 2*tq)     * 24 + col]);
                uint32_t h0 = __half_as_ushort(Vb[(k0 + 2*tq + 1) * 24 + col]);
                uint32_t l1 = __half_as_ushort(Vb[(k0 + 2*tq + 8) * 24 + col]);
                uint32_t h1 = __half_as_ushort(Vb[(k0 + 2*tq + 9) * 24 + col]);
                bq[nf][0] = l0 | (h0 << 16);
                bq[nf][1] = l1 | (h1 << 16);
            }
            #pragma unroll
            for (int mf = 0; mf < 2; mf++)
                #pragma unroll
                for (int nf = 0; nf < 2; nf++)
                    MMA_F16(acc2[mf][nf][0], acc2[mf][nf][1], acc2[mf][nf][2], acc2[mf][nf][3],
                            a[mf][0], a[mf][1], a[mf][2], a[mf][3],
                            bq[nf][0], bq[nf][1]);
        }

        // fragments -> OS [o][t][9] + px
        #pragma unroll
        for (int mf = 0; mf < 2; mf++) {
            int t0 = mf * 16 + g;
            #pragma unroll
            for (int nf = 0; nf < 2; nf++) {
                int o0 = nf * 8 + tq * 2;
                OS[(o0*32 + t0)*9 + px]       = acc2[mf][nf][0];
                OS[((o0+1)*32 + t0)*9 + px]   = acc2[mf][nf][1];
                OS[(o0*32 + t0+8)*9 + px]     = acc2[mf][nf][2];
                OS[((o0+1)*32 + t0+8)*9 + px] = acc2[mf][nf][3];
            }
        }
        __syncthreads();

        // OS + x -> out
        #pragma unroll
        for (int r = 0; r < 2; r++) {
            int row = r * 256 + tid;
            int o = row >> 5, t = row & 31;
            const float* osb = OS + (o*32 + t) * 9;
            float* ob = out + ((size_t)((b*512 + oc + o) * 32 + t)) * 1024 + hw0;
            float4 v0 = make_float4(osb[0] + xa[r][0].x, osb[1] + xa[r][0].y,
                                    osb[2] + xa[r][0].z, osb[3] + xa[r][0].w);
            float4 v1 = make_float4(osb[4] + xa[r][1].x, osb[5] + xa[r][1].y,
                                    osb[6] + xa[r][1].z, osb[7] + xa[r][1].w);
            *reinterpret_cast<float4*>(ob)     = v0;
            *reinterpret_cast<float4*>(ob + 4) = v1;
        }
        // top-of-next-iter sync separates OS reads from next writes
    }
}

// ---------------------------------------------------------------------------
extern "C" void kernel_launch(void* const* d_in, const int* in_sizes, int n_in,
                              void* d_out, int out_size)
{
    const float* x     = (const float*)d_in[0];
    const float* gamma = (const float*)d_in[1];
    const float* beta  = (const float*)d_in[2];
    const float* wq    = (const float*)d_in[3];
    const float* wk    = (const float*)d_in[4];
    const float* wv    = (const float*)d_in[5];
    const float* wproj = (const float*)d_in[6];
    float* out = (float*)d_out;

    cudaFuncSetAttribute(gemm_uv_f16, cudaFuncAttributeMaxDynamicSharedMemorySize,
                         GEMM_SMEM);
    cudaFuncSetAttribute(attn_f16, cudaFuncAttributeMaxDynamicSharedMemorySize,
                         ATTN_SMEM);

    prep_w2<<<1024, 256>>>(wq, wk, wv, wproj, gamma, beta);
    conv_x16<<<dim3(512, 8, B_), 256>>>(x);
    reduce_stats<<<128, 128>>>();
    gemm_uv_f16<<<dim3(8, 256, B_), 128, GEMM_SMEM>>>();
    attn_f16<<<512, 256, ATTN_SMEM>>>(x, gamma, beta, out);
}